// round 1
// baseline (speedup 1.0000x reference)
#include <cuda_runtime.h>
#include <cstdint>
#include <cstddef>

#define B_ 2
#define N_ 50000
#define E_ 500000
#define D_ 128
#define O_ 128
#define K_ 384
#define M_ (B_*N_)

// Scratch (device globals: no allocation allowed in kernel_launch)
__device__ float g_XS[(size_t)B_ * N_ * D_];   // scatter-sum of x[b, src] by dst (51.2 MB)
__device__ float g_EA[(size_t)N_ * D_];        // scatter-sum of edge_attr by dst (25.6 MB)
__device__ float g_cnt[N_];                    // in-degree counts
__device__ float g_Wc[K_ * O_];                // W_msg @ W_upd
__device__ float g_bmu[O_];                    // b_msg @ W_upd

// ---------------------------------------------------------------------------
// Zero the accumulators (float4 stores)
// ---------------------------------------------------------------------------
__global__ void zero_kernel() {
    const size_t nxs4 = (size_t)B_ * N_ * D_ / 4;
    const size_t nea4 = (size_t)N_ * D_ / 4;
    size_t i = (size_t)blockIdx.x * blockDim.x + threadIdx.x;
    float4 z = make_float4(0.f, 0.f, 0.f, 0.f);
    if (i < nxs4) {
        reinterpret_cast<float4*>(g_XS)[i] = z;
    } else if (i < nxs4 + nea4) {
        reinterpret_cast<float4*>(g_EA)[i - nxs4] = z;
    } else if (i < nxs4 + nea4 + N_) {
        g_cnt[i - nxs4 - nea4] = 0.f;
    }
}

// ---------------------------------------------------------------------------
// W_comb = W_msg @ W_upd  (384x128 @ 128x128), bmu = b_msg @ W_upd
// ---------------------------------------------------------------------------
__global__ void combine_weights(const float* __restrict__ Wm,
                                const float* __restrict__ Wu,
                                const float* __restrict__ bm) {
    int idx = blockIdx.x * blockDim.x + threadIdx.x;
    if (idx < K_ * O_) {
        int k = idx >> 7;
        int o = idx & 127;
        float s = 0.f;
        #pragma unroll 8
        for (int j = 0; j < O_; ++j)
            s = fmaf(Wm[k * O_ + j], Wu[j * O_ + o], s);
        g_Wc[idx] = s;
    }
    if (idx < O_) {
        float s = 0.f;
        for (int j = 0; j < O_; ++j)
            s = fmaf(bm[j], Wu[j * O_ + idx], s);
        g_bmu[idx] = s;
    }
}

// ---------------------------------------------------------------------------
// Edge scatter: one warp per edge. Lane l handles channels [4l, 4l+4).
//   g_EA[dst]      += edge_attr[e]
//   g_XS[b=0, dst] += x[0, src]
//   g_XS[b=1, dst] += x[1, src]
//   g_cnt[dst]     += 1
// Uses vectorized red.global.add.v4.f32 (sm_90+) to quarter atomic op count.
// ---------------------------------------------------------------------------
__device__ __forceinline__ void red_add_v4(float* addr, float4 v) {
    asm volatile("red.global.add.v4.f32 [%0], {%1, %2, %3, %4};"
                 :: "l"(addr), "f"(v.x), "f"(v.y), "f"(v.z), "f"(v.w)
                 : "memory");
}

__global__ void edge_scatter(const float* __restrict__ x,
                             const int*   __restrict__ ei,
                             const float* __restrict__ ea) {
    int e = (int)(((size_t)blockIdx.x * blockDim.x + threadIdx.x) >> 5);
    int lane = threadIdx.x & 31;
    if (e >= E_) return;

    int src = ei[e];
    int dst = ei[E_ + e];

    float4 va = reinterpret_cast<const float4*>(ea + (size_t)e * D_)[lane];
    float4 v0 = reinterpret_cast<const float4*>(x + (size_t)src * D_)[lane];
    float4 v1 = reinterpret_cast<const float4*>(x + ((size_t)N_ + src) * D_)[lane];

    red_add_v4(&g_EA[(size_t)dst * D_ + lane * 4], va);
    red_add_v4(&g_XS[(size_t)dst * D_ + lane * 4], v0);
    red_add_v4(&g_XS[((size_t)N_ + dst) * D_ + lane * 4], v1);

    if (lane == 0) atomicAdd(&g_cnt[dst], 1.0f);
}

// ---------------------------------------------------------------------------
// Fused node GEMM:
//   A[r] = [ inv(r)*g_XS[r] , cc(r)*x[r] , inv(r)*g_EA[r%N] ]   (row of 384)
//   out[r] = A[r] @ W_comb + cc(r)*bmu + b_upd
// where inv = 1/max(cnt,1), cc = (cnt>0 ? 1 : 0), r = b*N + n.
// Tiling: 128x128 block tile, BK=16, 256 threads, 8x8 per thread, double buf.
// ---------------------------------------------------------------------------
__global__ __launch_bounds__(256, 2)
void fused_gemm(const float* __restrict__ x,
                const float* __restrict__ bu,
                float* __restrict__ out)
{
    __shared__ float As[2][16][128];
    __shared__ float Bs[2][16][128];
    __shared__ float inv_s[128], cc_s[128], bmu_s[128], bu_s[128];

    const int tid = threadIdx.x;
    const int r0  = blockIdx.x * 128;
    const int tx  = tid & 15;
    const int ty  = tid >> 4;

    if (tid < 128) {
        int r = r0 + tid;
        float inv = 0.f, cc = 0.f;
        if (r < M_) {
            int n = (r >= N_) ? (r - N_) : r;
            float c = g_cnt[n];
            float mc = fmaxf(c, 1.0f);
            inv = 1.0f / mc;
            cc  = (c > 0.f) ? 1.f : 0.f;
        }
        inv_s[tid] = inv;
        cc_s[tid]  = cc;
        bmu_s[tid] = g_bmu[tid];
        bu_s[tid]  = bu[tid];
    }
    __syncthreads();

    // A-tile loader: 128 rows x 16 cols = 512 float4, 2 per thread.
    auto loadA = [&](int kb, int s, float4& v, float& sc, int& m, int& kc) {
        int f  = tid + s * 256;
        m      = f >> 2;
        int jj = f & 3;
        int phase = kb >> 7;                 // 0: XS(src), 1: x(dst), 2: EA
        int kof4  = ((kb & 127) >> 2) + jj;  // float4 index within source row
        int r  = r0 + m;
        int rc = (r < M_) ? r : (M_ - 1);
        const float* base;
        if (phase == 0)      base = g_XS + (size_t)rc * 128;
        else if (phase == 1) base = x    + (size_t)rc * 128;
        else {
            int n = (rc >= N_) ? (rc - N_) : rc;
            base = g_EA + (size_t)n * 128;
        }
        v  = reinterpret_cast<const float4*>(base)[kof4];
        sc = (phase == 1) ? cc_s[m] : inv_s[m];
        kc = jj * 4;
    };
    // B-tile loader: 16 rows x 128 cols of W_comb, 2 float4 per thread.
    auto loadB = [&](int kb, int s, float4& v, int& kr, int& c4) {
        int f  = tid + s * 256;
        kr     = f >> 5;
        int cg = f & 31;
        v  = reinterpret_cast<const float4*>(g_Wc + (size_t)(kb + kr) * 128)[cg];
        c4 = cg * 4;
    };

    // Prologue: tile 0 into buffer 0
    {
        float4 av, bv; float sc; int m, kc, kr, c4;
        #pragma unroll
        for (int s = 0; s < 2; ++s) {
            loadA(0, s, av, sc, m, kc);
            As[0][kc + 0][m] = av.x * sc;
            As[0][kc + 1][m] = av.y * sc;
            As[0][kc + 2][m] = av.z * sc;
            As[0][kc + 3][m] = av.w * sc;
            loadB(0, s, bv, kr, c4);
            *reinterpret_cast<float4*>(&Bs[0][kr][c4]) = bv;
        }
    }
    __syncthreads();

    float acc[8][8];
    #pragma unroll
    for (int i = 0; i < 8; ++i)
        #pragma unroll
        for (int j = 0; j < 8; ++j) acc[i][j] = 0.f;

    const int NT = K_ / 16;  // 24
    for (int kt = 0; kt < NT; ++kt) {
        int cur = kt & 1;

        float4 av[2], bv[2]; float sc[2];
        int am[2], akc[2], bkr[2], bc4[2];
        if (kt + 1 < NT) {
            #pragma unroll
            for (int s = 0; s < 2; ++s) {
                loadA((kt + 1) * 16, s, av[s], sc[s], am[s], akc[s]);
                loadB((kt + 1) * 16, s, bv[s], bkr[s], bc4[s]);
            }
        }

        #pragma unroll
        for (int k = 0; k < 16; ++k) {
            float4 a0 = *reinterpret_cast<const float4*>(&As[cur][k][ty * 4]);
            float4 a1 = *reinterpret_cast<const float4*>(&As[cur][k][ty * 4 + 64]);
            float4 b0 = *reinterpret_cast<const float4*>(&Bs[cur][k][tx * 4]);
            float4 b1 = *reinterpret_cast<const float4*>(&Bs[cur][k][tx * 4 + 64]);
            float a[8] = {a0.x, a0.y, a0.z, a0.w, a1.x, a1.y, a1.z, a1.w};
            float b[8] = {b0.x, b0.y, b0.z, b0.w, b1.x, b1.y, b1.z, b1.w};
            #pragma unroll
            for (int i = 0; i < 8; ++i)
                #pragma unroll
                for (int j = 0; j < 8; ++j)
                    acc[i][j] = fmaf(a[i], b[j], acc[i][j]);
        }

        if (kt + 1 < NT) {
            int nb = cur ^ 1;
            #pragma unroll
            for (int s = 0; s < 2; ++s) {
                As[nb][akc[s] + 0][am[s]] = av[s].x * sc[s];
                As[nb][akc[s] + 1][am[s]] = av[s].y * sc[s];
                As[nb][akc[s] + 2][am[s]] = av[s].z * sc[s];
                As[nb][akc[s] + 3][am[s]] = av[s].w * sc[s];
                *reinterpret_cast<float4*>(&Bs[nb][bkr[s]][bc4[s]]) = bv[s];
            }
            __syncthreads();
        }
    }

    // Epilogue
    #pragma unroll
    for (int i = 0; i < 8; ++i) {
        int m = (i < 4) ? (ty * 4 + i) : (64 + ty * 4 + (i - 4));
        int r = r0 + m;
        if (r < M_) {
            float ccb = cc_s[m];
            int n0 = tx * 4, n1 = 64 + tx * 4;
            float4 v0, v1;
            v0.x = acc[i][0] + ccb * bmu_s[n0 + 0] + bu_s[n0 + 0];
            v0.y = acc[i][1] + ccb * bmu_s[n0 + 1] + bu_s[n0 + 1];
            v0.z = acc[i][2] + ccb * bmu_s[n0 + 2] + bu_s[n0 + 2];
            v0.w = acc[i][3] + ccb * bmu_s[n0 + 3] + bu_s[n0 + 3];
            v1.x = acc[i][4] + ccb * bmu_s[n1 + 0] + bu_s[n1 + 0];
            v1.y = acc[i][5] + ccb * bmu_s[n1 + 1] + bu_s[n1 + 1];
            v1.z = acc[i][6] + ccb * bmu_s[n1 + 2] + bu_s[n1 + 2];
            v1.w = acc[i][7] + ccb * bmu_s[n1 + 3] + bu_s[n1 + 3];
            *reinterpret_cast<float4*>(&out[(size_t)r * 128 + n0]) = v0;
            *reinterpret_cast<float4*>(&out[(size_t)r * 128 + n1]) = v1;
        }
    }
}

// ---------------------------------------------------------------------------
// Launch
// ---------------------------------------------------------------------------
extern "C" void kernel_launch(void* const* d_in, const int* in_sizes, int n_in,
                              void* d_out, int out_size) {
    const float* x  = (const float*)d_in[0];   // (B, N, D)
    const int*   ei = (const int*)  d_in[1];   // (2, E)
    const float* ea = (const float*)d_in[2];   // (E, D)
    const float* Wm = (const float*)d_in[3];   // (3D, O)
    const float* bm = (const float*)d_in[4];   // (O,)
    const float* Wu = (const float*)d_in[5];   // (O, O)
    const float* bu = (const float*)d_in[6];   // (O,)
    float* out = (float*)d_out;                // (B, N, O)

    const size_t ztotal = (size_t)B_ * N_ * D_ / 4 + (size_t)N_ * D_ / 4 + N_;
    zero_kernel<<<(unsigned)((ztotal + 255) / 256), 256>>>();
    combine_weights<<<(K_ * O_ + 255) / 256, 256>>>(Wm, Wu, bm);
    edge_scatter<<<(int)(((size_t)E_ * 32 + 255) / 256), 256>>>(x, ei, ea);
    fused_gemm<<<(M_ + 127) / 128, 256>>>(x, bu, out);
}